// round 6
// baseline (speedup 1.0000x reference)
#include <cuda_runtime.h>
#include <cuda_bf16.h>
#include <cstdint>

#define NN 4096
#define DD 512
#define F1V 64
#define HH 4
#define MAXNBR 128

__device__ __forceinline__ void mma_bf16(float* c, const uint32_t* a, const uint32_t* b) {
    asm volatile(
        "mma.sync.aligned.m16n8k16.row.col.f32.bf16.bf16.f32 "
        "{%0,%1,%2,%3}, {%4,%5,%6,%7}, {%8,%9}, {%0,%1,%2,%3};"
        : "+f"(c[0]), "+f"(c[1]), "+f"(c[2]), "+f"(c[3])
        : "r"(a[0]), "r"(a[1]), "r"(a[2]), "r"(a[3]), "r"(b[0]), "r"(b[1]));
}

__device__ __forceinline__ void split_bf(float f, unsigned short& hi, unsigned short& lo) {
    __nv_bfloat16 h = __float2bfloat16(f);
    float r = f - __bfloat162float(h);
    __nv_bfloat16 l = __float2bfloat16(r);
    hi = *reinterpret_cast<unsigned short*>(&h);
    lo = *reinterpret_cast<unsigned short*>(&l);
}

// ---------------- device scratch (static, no allocation) ----------------
__device__ int      g_cnt[NN];
__device__ int      g_cols[NN * MAXNBR];
__device__ uint16_t g_xhi[NN * DD];
__device__ uint16_t g_xlo[NN * DD];
__device__ uint16_t g_Wthi[HH * F1V * DD];     // [h][n][k] transposed
__device__ uint16_t g_Wtlo[HH * F1V * DD];
__device__ uint16_t g_Wathi[F1V * 256];        // [n][k]
__device__ uint16_t g_Watlo[F1V * 256];
__device__ float    g_Wh[HH * NN * F1V];       // [h][n][64]
__device__ float    g_src[HH * NN];
__device__ float    g_dst[HH * NN];
__device__ uint16_t g_cat_hi[NN * 256];        // [n][h*64+f]
__device__ uint16_t g_cat_lo[NN * 256];
__device__ float    g_Whc[NN * F1V];
__device__ float    g_srcc[NN];
__device__ float    g_dstc[NN];
__device__ float    g_t1[NN * 32];
__device__ float    g_t23[NN * 32];
__device__ float    g_z[NN * 16];

// ---------------- 1: CSR build (warp per row) ---------------------------
__global__ void k_build_csr(const float* __restrict__ adj) {
    int wid = threadIdx.x >> 5, lane = threadIdx.x & 31;
    int row = blockIdx.x * 8 + wid;
    const float4* arow = reinterpret_cast<const float4*>(adj + (size_t)row * NN);
    int cnt = 0;
    int* cols = g_cols + row * MAXNBR;
    for (int step = 0; step < 32; ++step) {
        float4 v = arow[step * 32 + lane];
        float vals[4] = {v.x, v.y, v.z, v.w};
        #pragma unroll
        for (int e = 0; e < 4; ++e) {
            bool p = vals[e] > 0.0f;
            unsigned m = __ballot_sync(0xffffffffu, p);
            if (p) {
                int pos = cnt + __popc(m & ((1u << lane) - 1u));
                if (pos < MAXNBR) cols[pos] = (step * 32 + lane) * 4 + e;
            }
            cnt += __popc(m);
        }
    }
    if (lane == 0) g_cnt[row] = cnt > MAXNBR ? MAXNBR : cnt;
}

// ---------------- 2: split x into bf16 hi/lo ----------------------------
__global__ void k_prep_x(const float* __restrict__ x) {
    int idx = blockIdx.x * 256 + threadIdx.x;       // over float4s
    float4 v = reinterpret_cast<const float4*>(x)[idx];
    unsigned short h0, l0, h1, l1, h2, l2, h3, l3;
    split_bf(v.x, h0, l0); split_bf(v.y, h1, l1);
    split_bf(v.z, h2, l2); split_bf(v.w, h3, l3);
    uint2 hv = make_uint2((uint32_t)h0 | ((uint32_t)h1 << 16),
                          (uint32_t)h2 | ((uint32_t)h3 << 16));
    uint2 lv = make_uint2((uint32_t)l0 | ((uint32_t)l1 << 16),
                          (uint32_t)l2 | ((uint32_t)l3 << 16));
    reinterpret_cast<uint2*>(g_xhi)[idx] = hv;
    reinterpret_cast<uint2*>(g_xlo)[idx] = lv;
}

// ---------------- 3: split+transpose weights ----------------------------
__global__ void k_prep_w(const float* __restrict__ W_heads, const float* __restrict__ W_att) {
    int idx = blockIdx.x * 256 + threadIdx.x;
    if (idx < HH * DD * F1V) {
        int n = idx & 63, k = (idx >> 6) & 511, h = idx >> 15;
        unsigned short hi, lo;
        split_bf(W_heads[idx], hi, lo);
        int o = (h * F1V + n) * DD + k;
        g_Wthi[o] = hi; g_Wtlo[o] = lo;
    } else {
        int i2 = idx - HH * DD * F1V;   // [256][64]
        int n = i2 & 63, k = i2 >> 6;
        unsigned short hi, lo;
        split_bf(W_att[i2], hi, lo);
        int o = n * 256 + k;
        g_Wathi[o] = hi; g_Watlo[o] = lo;
    }
}

// ---------------- 4: mma.sync GEMM (M tile 128, N=64), fused src/dst ----
// 256 thr = 8 warps, warp handles 16 rows x 64 cols.
// hi/lo split: acc += Ahi*Bhi + Alo*Bhi + Ahi*Blo
__global__ void __launch_bounds__(256)
k_gemm_mma(const float* __restrict__ avec, int K, int sel) {
    __shared__ float s_a[128];
    int tid = threadIdx.x;
    int w = tid >> 5, lane = tid & 31;
    int head = blockIdx.y;
    int m0 = blockIdx.x * 128;
    int rbase = m0 + w * 16;

    const uint16_t *Ahi, *Alo, *Bhi, *Blo;
    float *oWh, *oSrc, *oDst;
    if (sel == 0) {
        Ahi = g_xhi; Alo = g_xlo;
        Bhi = g_Wthi + (size_t)head * F1V * DD;
        Blo = g_Wtlo + (size_t)head * F1V * DD;
        oWh = g_Wh + (size_t)head * NN * F1V;
        oSrc = g_src + head * NN; oDst = g_dst + head * NN;
    } else {
        Ahi = g_cat_hi; Alo = g_cat_lo;
        Bhi = g_Wathi; Blo = g_Watlo;
        oWh = g_Whc; oSrc = g_srcc; oDst = g_dstc;
    }
    if (tid < 128) s_a[tid] = avec[head * 128 + tid];
    __syncthreads();

    int g = lane >> 2, t = lane & 3;
    float acc[8][4] = {};
    int nk = K >> 4;

    const uint16_t* arow0 = Ahi + (size_t)(rbase + g) * K;
    const uint16_t* arow1 = Ahi + (size_t)(rbase + g + 8) * K;
    const uint16_t* arow0l = Alo + (size_t)(rbase + g) * K;
    const uint16_t* arow1l = Alo + (size_t)(rbase + g + 8) * K;

    for (int kc = 0; kc < nk; ++kc) {
        int k0 = kc << 4;
        uint32_t ah[4], al[4];
        ah[0] = *reinterpret_cast<const uint32_t*>(arow0 + k0 + 2 * t);
        ah[1] = *reinterpret_cast<const uint32_t*>(arow1 + k0 + 2 * t);
        ah[2] = *reinterpret_cast<const uint32_t*>(arow0 + k0 + 2 * t + 8);
        ah[3] = *reinterpret_cast<const uint32_t*>(arow1 + k0 + 2 * t + 8);
        al[0] = *reinterpret_cast<const uint32_t*>(arow0l + k0 + 2 * t);
        al[1] = *reinterpret_cast<const uint32_t*>(arow1l + k0 + 2 * t);
        al[2] = *reinterpret_cast<const uint32_t*>(arow0l + k0 + 2 * t + 8);
        al[3] = *reinterpret_cast<const uint32_t*>(arow1l + k0 + 2 * t + 8);
        #pragma unroll
        for (int nj = 0; nj < 8; ++nj) {
            const uint16_t* brow = Bhi + (size_t)(nj * 8 + g) * K;
            const uint16_t* browl = Blo + (size_t)(nj * 8 + g) * K;
            uint32_t bh[2], bl[2];
            bh[0] = *reinterpret_cast<const uint32_t*>(brow + k0 + 2 * t);
            bh[1] = *reinterpret_cast<const uint32_t*>(brow + k0 + 2 * t + 8);
            bl[0] = *reinterpret_cast<const uint32_t*>(browl + k0 + 2 * t);
            bl[1] = *reinterpret_cast<const uint32_t*>(browl + k0 + 2 * t + 8);
            mma_bf16(acc[nj], ah, bh);
            mma_bf16(acc[nj], al, bh);
            mma_bf16(acc[nj], ah, bl);
        }
    }

    // write Wh + fused src/dst logits
    int r0 = rbase + g, r1 = rbase + g + 8;
    float sp0 = 0, sp1 = 0, dp0 = 0, dp1 = 0;
    #pragma unroll
    for (int nj = 0; nj < 8; ++nj) {
        int cb = nj * 8 + 2 * t;
        *reinterpret_cast<float2*>(oWh + (size_t)r0 * 64 + cb) = make_float2(acc[nj][0], acc[nj][1]);
        *reinterpret_cast<float2*>(oWh + (size_t)r1 * 64 + cb) = make_float2(acc[nj][2], acc[nj][3]);
        float a0s = s_a[cb], a1s = s_a[cb + 1];
        float a0d = s_a[64 + cb], a1d = s_a[64 + cb + 1];
        sp0 += acc[nj][0] * a0s + acc[nj][1] * a1s;
        sp1 += acc[nj][2] * a0s + acc[nj][3] * a1s;
        dp0 += acc[nj][0] * a0d + acc[nj][1] * a1d;
        dp1 += acc[nj][2] * a0d + acc[nj][3] * a1d;
    }
    #pragma unroll
    for (int off = 1; off < 4; off <<= 1) {
        sp0 += __shfl_xor_sync(0xffffffffu, sp0, off);
        sp1 += __shfl_xor_sync(0xffffffffu, sp1, off);
        dp0 += __shfl_xor_sync(0xffffffffu, dp0, off);
        dp1 += __shfl_xor_sync(0xffffffffu, dp1, off);
    }
    if (t == 0) {
        oSrc[r0] = sp0; oSrc[r1] = sp1;
        oDst[r0] = dp0; oDst[r1] = dp1;
    }
}

// ---------------- 5: sparse GAT softmax + aggregate + ELU ---------------
__global__ void k_gat_aggr(const float* __restrict__ W1, int sel) {
    __shared__ float2 s_wc[8][MAXNBR];
    int wid = threadIdx.x >> 5, lane = threadIdx.x & 31;
    int wg = blockIdx.x * 8 + wid;
    int h, row;
    if (sel) { h = 0; row = wg; } else { h = wg & 3; row = wg >> 2; }
    const float* Wh  = sel ? g_Whc  : g_Wh;
    const float* src = sel ? g_srcc : g_src;
    const float* dst = sel ? g_dstc : g_dst;

    int cnt = g_cnt[row];
    const int* cols = g_cols + row * MAXNBR;
    float si = src[h * NN + row];
    const float* dsth = dst + (size_t)h * NN;

    float sum = 0.0f;
    #pragma unroll
    for (int t = 0; t < 4; ++t) {
        int idx = t * 32 + lane;
        float e = 0.0f; int c = 0;
        if (idx < cnt) {
            c = cols[idx];
            float v = si + __ldg(dsth + c);
            v = v > 0.0f ? v : 0.2f * v;           // LeakyReLU (logits bounded -> no max)
            e = __expf(v);
        }
        s_wc[wid][idx] = make_float2(e, __int_as_float(c));
        sum += e;
    }
    #pragma unroll
    for (int o = 16; o; o >>= 1) sum += __shfl_xor_sync(0xffffffffu, sum, o);
    float inv = 1.0f / sum;
    __syncwarp();

    const float* Whh = Wh + (size_t)h * NN * 64 + 2 * lane;
    float2 A0 = {0, 0}, A1 = {0, 0}, A2 = {0, 0}, A3 = {0, 0};
    int j = 0;
    for (; j + 4 <= cnt; j += 4) {
        float2 p0 = s_wc[wid][j],     p1 = s_wc[wid][j + 1];
        float2 p2 = s_wc[wid][j + 2], p3 = s_wc[wid][j + 3];
        float2 v0 = *reinterpret_cast<const float2*>(Whh + (size_t)__float_as_int(p0.y) * 64);
        float2 v1 = *reinterpret_cast<const float2*>(Whh + (size_t)__float_as_int(p1.y) * 64);
        float2 v2 = *reinterpret_cast<const float2*>(Whh + (size_t)__float_as_int(p2.y) * 64);
        float2 v3 = *reinterpret_cast<const float2*>(Whh + (size_t)__float_as_int(p3.y) * 64);
        A0.x += p0.x * v0.x; A0.y += p0.x * v0.y;
        A1.x += p1.x * v1.x; A1.y += p1.x * v1.y;
        A2.x += p2.x * v2.x; A2.y += p2.x * v2.y;
        A3.x += p3.x * v3.x; A3.y += p3.x * v3.y;
    }
    for (; j < cnt; ++j) {
        float2 p0 = s_wc[wid][j];
        float2 v0 = *reinterpret_cast<const float2*>(Whh + (size_t)__float_as_int(p0.y) * 64);
        A0.x += p0.x * v0.x; A0.y += p0.x * v0.y;
    }
    float a0 = (A0.x + A1.x + A2.x + A3.x) * inv;
    float a1 = (A0.y + A1.y + A2.y + A3.y) * inv;
    a0 = a0 > 0.0f ? a0 : __expf(a0) - 1.0f;       // ELU
    a1 = a1 > 0.0f ? a1 : __expf(a1) - 1.0f;

    if (sel == 0) {
        unsigned short h0, l0, h1, l1;
        split_bf(a0, h0, l0); split_bf(a1, h1, l1);
        int o32 = row * 128 + h * 32 + lane;        // u32 index into [n][256] u16
        reinterpret_cast<uint32_t*>(g_cat_hi)[o32] = (uint32_t)h0 | ((uint32_t)h1 << 16);
        reinterpret_cast<uint32_t*>(g_cat_lo)[o32] = (uint32_t)l0 | ((uint32_t)l1 << 16);
    } else {
        float acc = 0.0f;
        #pragma unroll
        for (int k = 0; k < 32; ++k) {
            float w0 = __shfl_sync(0xffffffffu, a0, k);
            float w1 = __shfl_sync(0xffffffffu, a1, k);
            acc += w0 * W1[(2 * k) * 32 + lane] + w1 * W1[(2 * k + 1) * 32 + lane];
        }
        g_t1[(size_t)row * 32 + lane] = acc;
    }
}

// ---------------- 6: h1 = relu(nbrsum(t1)); t23 = h1@[W2|W3] ------------
__global__ void k_nbr_t23(const float* __restrict__ W2, const float* __restrict__ W3) {
    int wid = threadIdx.x >> 5, lane = threadIdx.x & 31;
    int row = blockIdx.x * 8 + wid;
    int cnt = g_cnt[row];
    const int* cols = g_cols + row * MAXNBR;
    float acc = 0.0f;
    for (int jj = 0; jj < cnt; ++jj) {
        int c = cols[jj];
        acc += g_t1[(size_t)c * 32 + lane];
    }
    float hv = fmaxf(acc, 0.0f);
    const float* W = (lane < 16) ? W2 : W3;
    int f = lane & 15;
    float acc2 = 0.0f;
    #pragma unroll
    for (int k = 0; k < 32; ++k) {
        float h = __shfl_sync(0xffffffffu, hv, k);
        acc2 += h * W[k * 16 + f];
    }
    g_t23[(size_t)row * 32 + lane] = acc2;
}

// ---------------- 7: mu/logvar = nbrsum, z = eps*exp(lv)+mu -------------
__global__ void k_final(const float* __restrict__ eps, float* __restrict__ out) {
    int wid = threadIdx.x >> 5, lane = threadIdx.x & 31;
    int row = blockIdx.x * 8 + wid;
    int cnt = g_cnt[row];
    const int* cols = g_cols + row * MAXNBR;
    float acc = 0.0f;
    for (int j = 0; j < cnt; ++j) {
        int c = cols[j];
        acc += g_t23[(size_t)c * 32 + lane];
    }
    float other = __shfl_xor_sync(0xffffffffu, acc, 16);
    size_t NNq = (size_t)NN * NN;
    if (lane < 16) {
        out[NNq + (size_t)row * 16 + lane] = acc;                          // mu
        float zz = eps[(size_t)row * 16 + lane] * __expf(other) + acc;
        g_z[(size_t)row * 16 + lane] = zz;
    } else {
        out[NNq + (size_t)NN * 16 + (size_t)row * 16 + (lane - 16)] = acc; // logvar
    }
}

// ---------------- 8: adj_rec = z @ z^T ----------------------------------
__global__ void k_adjrec(float* __restrict__ out) {
    __shared__ float zi[64 * 17];
    __shared__ float zj[64 * 17];
    int i0 = blockIdx.y * 64, j0 = blockIdx.x * 64;
    int tid = threadIdx.x;
    for (int l = tid; l < 1024; l += 256) {
        int r = l >> 4, k = l & 15;
        zi[r * 17 + k] = g_z[(size_t)(i0 + r) * 16 + k];
        zj[r * 17 + k] = g_z[(size_t)(j0 + r) * 16 + k];
    }
    __syncthreads();
    int ty = tid >> 4, tx = tid & 15;
    float acc[4][4] = {};
    #pragma unroll
    for (int k = 0; k < 16; ++k) {
        float av[4], bv[4];
        #pragma unroll
        for (int i = 0; i < 4; ++i) av[i] = zi[(ty * 4 + i) * 17 + k];
        #pragma unroll
        for (int j = 0; j < 4; ++j) bv[j] = zj[(tx * 4 + j) * 17 + k];
        #pragma unroll
        for (int i = 0; i < 4; ++i)
            #pragma unroll
            for (int j = 0; j < 4; ++j)
                acc[i][j] += av[i] * bv[j];
    }
    #pragma unroll
    for (int i = 0; i < 4; ++i) {
        float4 v = make_float4(acc[i][0], acc[i][1], acc[i][2], acc[i][3]);
        *reinterpret_cast<float4*>(out + (size_t)(i0 + ty * 4 + i) * NN + j0 + tx * 4) = v;
    }
}

// ---------------- launch ------------------------------------------------
extern "C" void kernel_launch(void* const* d_in, const int* in_sizes, int n_in,
                              void* d_out, int out_size) {
    const float* x       = (const float*)d_in[0];
    const float* adj     = (const float*)d_in[1];
    const float* W_heads = (const float*)d_in[2];
    const float* a_heads = (const float*)d_in[3];
    const float* W_att   = (const float*)d_in[4];
    const float* a_att   = (const float*)d_in[5];
    const float* W1      = (const float*)d_in[6];
    const float* W2      = (const float*)d_in[7];
    const float* W3      = (const float*)d_in[8];
    const float* eps     = (const float*)d_in[9];
    float* out = (float*)d_out;
    (void)in_sizes; (void)n_in; (void)out_size;

    k_build_csr<<<NN / 8, 256>>>(adj);
    k_prep_x<<<(NN * DD / 4) / 256, 256>>>(x);
    k_prep_w<<<(HH * DD * F1V + 256 * F1V) / 256, 256>>>(W_heads, W_att);
    k_gemm_mma<<<dim3(NN / 128, HH), 256>>>(a_heads, DD, 0);
    k_gat_aggr<<<(NN * HH) / 8, 256>>>(W1, 0);
    k_gemm_mma<<<dim3(NN / 128, 1), 256>>>(a_att, 256, 1);
    k_gat_aggr<<<NN / 8, 256>>>(W1, 1);
    k_nbr_t23<<<NN / 8, 256>>>(W2, W3);
    k_final<<<NN / 8, 256>>>(eps, out);
    k_adjrec<<<dim3(NN / 64, NN / 64), 256>>>(out);
}

// round 7
// speedup vs baseline: 1.7878x; 1.7878x over previous
#include <cuda_runtime.h>
#include <cuda_bf16.h>
#include <cstdint>

#define NN 4096
#define DD 512
#define F1V 64
#define HH 4
#define MAXNBR 128

__device__ __forceinline__ uint32_t smem_u32(const void* p) {
    uint32_t a;
    asm("{ .reg .u64 t; cvta.to.shared.u64 t, %1; cvt.u32.u64 %0, t; }" : "=r"(a) : "l"(p));
    return a;
}
__device__ __forceinline__ void mma_bf16(float* c, const uint32_t* a, const uint32_t* b) {
    asm volatile(
        "mma.sync.aligned.m16n8k16.row.col.f32.bf16.bf16.f32 "
        "{%0,%1,%2,%3}, {%4,%5,%6,%7}, {%8,%9}, {%0,%1,%2,%3};"
        : "+f"(c[0]), "+f"(c[1]), "+f"(c[2]), "+f"(c[3])
        : "r"(a[0]), "r"(a[1]), "r"(a[2]), "r"(a[3]), "r"(b[0]), "r"(b[1]));
}
__device__ __forceinline__ void ldsm4(uint32_t* r, uint32_t addr) {
    asm volatile("ldmatrix.sync.aligned.m8n8.x4.shared.b16 {%0,%1,%2,%3}, [%4];"
        : "=r"(r[0]), "=r"(r[1]), "=r"(r[2]), "=r"(r[3]) : "r"(addr));
}
__device__ __forceinline__ void split_bf(float f, unsigned short& hi, unsigned short& lo) {
    __nv_bfloat16 h = __float2bfloat16(f);
    float r = f - __bfloat162float(h);
    __nv_bfloat16 l = __float2bfloat16(r);
    hi = *reinterpret_cast<unsigned short*>(&h);
    lo = *reinterpret_cast<unsigned short*>(&l);
}

// ---------------- device scratch (static, no allocation) ----------------
__device__ int      g_cnt[NN];
__device__ int      g_cols[NN * MAXNBR];
__device__ uint16_t g_xhi[NN * DD];
__device__ uint16_t g_xlo[NN * DD];
__device__ uint16_t g_Wthi[HH * F1V * DD];     // [h][n][k] transposed
__device__ uint16_t g_Wtlo[HH * F1V * DD];
__device__ uint16_t g_Wathi[F1V * 256];        // [n][k]
__device__ uint16_t g_Watlo[F1V * 256];
__device__ float    g_Wh[HH * NN * F1V];       // [h][n][64]
__device__ float    g_src[HH * NN];
__device__ float    g_dst[HH * NN];
__device__ uint16_t g_cat_hi[NN * 256];        // [n][h*64+f]
__device__ uint16_t g_cat_lo[NN * 256];
__device__ float    g_Whc[NN * F1V];
__device__ float    g_srcc[NN];
__device__ float    g_dstc[NN];
__device__ float    g_t1[NN * 32];
__device__ float    g_t23[NN * 32];
__device__ float    g_z[NN * 16];

// ---------------- 1: CSR build (warp per row) ---------------------------
__global__ void k_build_csr(const float* __restrict__ adj) {
    int wid = threadIdx.x >> 5, lane = threadIdx.x & 31;
    int row = blockIdx.x * 8 + wid;
    const float4* arow = reinterpret_cast<const float4*>(adj + (size_t)row * NN);
    int cnt = 0;
    int* cols = g_cols + row * MAXNBR;
    for (int step = 0; step < 32; ++step) {
        float4 v = arow[step * 32 + lane];
        float vals[4] = {v.x, v.y, v.z, v.w};
        #pragma unroll
        for (int e = 0; e < 4; ++e) {
            bool p = vals[e] > 0.0f;
            unsigned m = __ballot_sync(0xffffffffu, p);
            if (p) {
                int pos = cnt + __popc(m & ((1u << lane) - 1u));
                if (pos < MAXNBR) cols[pos] = (step * 32 + lane) * 4 + e;
            }
            cnt += __popc(m);
        }
    }
    if (lane == 0) g_cnt[row] = cnt > MAXNBR ? MAXNBR : cnt;
}

// ---------------- 2: split x into bf16 hi/lo ----------------------------
__global__ void k_prep_x(const float* __restrict__ x) {
    int idx = blockIdx.x * 256 + threadIdx.x;       // over float4s
    float4 v = reinterpret_cast<const float4*>(x)[idx];
    unsigned short h0, l0, h1, l1, h2, l2, h3, l3;
    split_bf(v.x, h0, l0); split_bf(v.y, h1, l1);
    split_bf(v.z, h2, l2); split_bf(v.w, h3, l3);
    uint2 hv = make_uint2((uint32_t)h0 | ((uint32_t)h1 << 16),
                          (uint32_t)h2 | ((uint32_t)h3 << 16));
    uint2 lv = make_uint2((uint32_t)l0 | ((uint32_t)l1 << 16),
                          (uint32_t)l2 | ((uint32_t)l3 << 16));
    reinterpret_cast<uint2*>(g_xhi)[idx] = hv;
    reinterpret_cast<uint2*>(g_xlo)[idx] = lv;
}

// ---------------- 3: split+transpose weights ----------------------------
__global__ void k_prep_w(const float* __restrict__ W_heads, const float* __restrict__ W_att) {
    int idx = blockIdx.x * 256 + threadIdx.x;
    if (idx < HH * DD * F1V) {
        int n = idx & 63, k = (idx >> 6) & 511, h = idx >> 15;
        unsigned short hi, lo;
        split_bf(W_heads[idx], hi, lo);
        int o = (h * F1V + n) * DD + k;
        g_Wthi[o] = hi; g_Wtlo[o] = lo;
    } else {
        int i2 = idx - HH * DD * F1V;   // [256][64]
        int n = i2 & 63, k = i2 >> 6;
        unsigned short hi, lo;
        split_bf(W_att[i2], hi, lo);
        int o = n * 256 + k;
        g_Wathi[o] = hi; g_Watlo[o] = lo;
    }
}

// ---------------- 4: smem-pipelined mma GEMM (M=128,N=64) + src/dst -----
// k-chunk 16, 2 stages. smem layout (bytes, 48B-padded rows):
//   A: stage*12288 + side*6144 + row*48 + unit*16      (rows 0..127)
//   B: 24576 + stage*6144 + side*3072 + row*48 + unit*16 (rows 0..63)
__global__ void __launch_bounds__(256)
k_gemm_mma(const float* __restrict__ avec, int K, int sel) {
    __shared__ __align__(16) unsigned char sm[36864];
    __shared__ float s_av[128];
    __shared__ float s_sp[2][128];
    __shared__ float s_dp[2][128];

    int tid = threadIdx.x;
    int w = tid >> 5, lane = tid & 31;
    int MW = (w & 3) * 32, NW = (w >> 2) * 32;
    int nwidx = w >> 2;
    int g = lane >> 2, t = lane & 3;
    int head = blockIdx.y;
    int m0 = blockIdx.x * 128;

    const uint16_t *Ahi, *Alo, *Bhi, *Blo;
    float *oWh, *oSrc, *oDst;
    if (sel == 0) {
        Ahi = g_xhi; Alo = g_xlo;
        Bhi = g_Wthi + (size_t)head * F1V * DD;
        Blo = g_Wtlo + (size_t)head * F1V * DD;
        oWh = g_Wh + (size_t)head * NN * F1V;
        oSrc = g_src + head * NN; oDst = g_dst + head * NN;
    } else {
        Ahi = g_cat_hi; Alo = g_cat_lo;
        Bhi = g_Wathi; Blo = g_Watlo;
        oWh = g_Whc; oSrc = g_srcc; oDst = g_dstc;
    }
    if (tid < 128) s_av[tid] = avec[head * 128 + tid];

    // LDG assignments
    int arow = tid >> 1, ahalf = tid & 1;           // A: 16B half of 32B chunk-row
    int brow = (tid & 127) >> 1, bhalf = tid & 1, bside = tid >> 7;
    const uint4* pAh = reinterpret_cast<const uint4*>(Ahi + (size_t)(m0 + arow) * K) + ahalf;
    const uint4* pAl = reinterpret_cast<const uint4*>(Alo + (size_t)(m0 + arow) * K) + ahalf;
    const uint16_t* Bsel = bside ? Blo : Bhi;
    const uint4* pB = reinterpret_cast<const uint4*>(Bsel + (size_t)brow * K) + bhalf;

    // STS byte offsets (stage 0)
    int stsA = arow * 48 + ahalf * 16;
    int stsB = 24576 + bside * 3072 + brow * 48 + bhalf * 16;

    // LDSM byte offsets (stage 0, side 0)
    uint32_t smb = smem_u32(sm);
    int offA0 = (MW + (lane & 15)) * 48 + (lane >> 4) * 16;
    int offA1 = (MW + 16 + (lane & 15)) * 48 + (lane >> 4) * 16;
    int offB0 = 24576 + (NW + ((lane >> 4) << 3) + (lane & 7)) * 48 + ((lane >> 3) & 1) * 16;
    int offB1 = offB0 + 16 * 48;

    float acc[2][4][4] = {};
    int nch = K >> 4;

    // prologue: chunk 0 -> stage 0
    uint4 rAh = pAh[0], rAl = pAl[0], rB = pB[0];
    *reinterpret_cast<uint4*>(sm + stsA) = rAh;
    *reinterpret_cast<uint4*>(sm + 6144 + stsA) = rAl;
    *reinterpret_cast<uint4*>(sm + stsB) = rB;

    for (int c = 0; c < nch; ++c) {
        __syncthreads();
        if (c + 1 < nch) {
            rAh = pAh[(c + 1) * 2];
            rAl = pAl[(c + 1) * 2];
            rB  = pB[(c + 1) * 2];
        }
        int sb = c & 1;
        uint32_t stA = smb + sb * 12288;
        uint32_t stB = smb + sb * 6144;
        uint32_t ah[2][4], al[2][4], bh[2][4], bl[2][4];
        ldsm4(ah[0], stA + offA0);
        ldsm4(ah[1], stA + offA1);
        ldsm4(al[0], stA + 6144 + offA0);
        ldsm4(al[1], stA + 6144 + offA1);
        ldsm4(bh[0], stB + offB0);
        ldsm4(bh[1], stB + offB1);
        ldsm4(bl[0], stB + 3072 + offB0);
        ldsm4(bl[1], stB + 3072 + offB1);
        #pragma unroll
        for (int i = 0; i < 2; ++i)
            #pragma unroll
            for (int jj = 0; jj < 4; ++jj) {
                float* cc = acc[i][jj];
                const uint32_t* bph = &bh[jj >> 1][(jj & 1) * 2];
                const uint32_t* bpl = &bl[jj >> 1][(jj & 1) * 2];
                mma_bf16(cc, ah[i], bph);
                mma_bf16(cc, al[i], bph);
                mma_bf16(cc, ah[i], bpl);
            }
        if (c + 1 < nch) {
            int s2 = (c + 1) & 1;
            *reinterpret_cast<uint4*>(sm + s2 * 12288 + stsA) = rAh;
            *reinterpret_cast<uint4*>(sm + s2 * 12288 + 6144 + stsA) = rAl;
            *reinterpret_cast<uint4*>(sm + s2 * 6144 + stsB) = rB;
        }
    }

    // epilogue: write Wh, fused src/dst partials
    #pragma unroll
    for (int i = 0; i < 2; ++i) {
        int r0 = MW + i * 16 + g;
        float sp0 = 0, sp1 = 0, dp0 = 0, dp1 = 0;
        #pragma unroll
        for (int jj = 0; jj < 4; ++jj) {
            int cb = NW + jj * 8 + 2 * t;
            *reinterpret_cast<float2*>(oWh + (size_t)(m0 + r0) * 64 + cb) =
                make_float2(acc[i][jj][0], acc[i][jj][1]);
            *reinterpret_cast<float2*>(oWh + (size_t)(m0 + r0 + 8) * 64 + cb) =
                make_float2(acc[i][jj][2], acc[i][jj][3]);
            float a0s = s_av[cb], a1s = s_av[cb + 1];
            float a0d = s_av[64 + cb], a1d = s_av[64 + cb + 1];
            sp0 += acc[i][jj][0] * a0s + acc[i][jj][1] * a1s;
            sp1 += acc[i][jj][2] * a0s + acc[i][jj][3] * a1s;
            dp0 += acc[i][jj][0] * a0d + acc[i][jj][1] * a1d;
            dp1 += acc[i][jj][2] * a0d + acc[i][jj][3] * a1d;
        }
        #pragma unroll
        for (int off = 1; off < 4; off <<= 1) {
            sp0 += __shfl_xor_sync(0xffffffffu, sp0, off);
            sp1 += __shfl_xor_sync(0xffffffffu, sp1, off);
            dp0 += __shfl_xor_sync(0xffffffffu, dp0, off);
            dp1 += __shfl_xor_sync(0xffffffffu, dp1, off);
        }
        if (t == 0) {
            s_sp[nwidx][r0] = sp0; s_sp[nwidx][r0 + 8] = sp1;
            s_dp[nwidx][r0] = dp0; s_dp[nwidx][r0 + 8] = dp1;
        }
    }
    __syncthreads();
    if (tid < 128) {
        oSrc[m0 + tid] = s_sp[0][tid] + s_sp[1][tid];
        oDst[m0 + tid] = s_dp[0][tid] + s_dp[1][tid];
    }
}

// ---------------- 5: sparse GAT softmax + aggregate + ELU ---------------
__global__ void k_gat_aggr(const float* __restrict__ W1, int sel) {
    __shared__ float2 s_wc[8][MAXNBR];
    int wid = threadIdx.x >> 5, lane = threadIdx.x & 31;
    int wg = blockIdx.x * 8 + wid;
    int h, row;
    if (sel) { h = 0; row = wg; } else { h = wg & 3; row = wg >> 2; }
    const float* Wh  = sel ? g_Whc  : g_Wh;
    const float* src = sel ? g_srcc : g_src;
    const float* dst = sel ? g_dstc : g_dst;

    int cnt = g_cnt[row];
    const int* cols = g_cols + row * MAXNBR;
    float si = src[h * NN + row];
    const float* dsth = dst + (size_t)h * NN;

    float sum = 0.0f;
    #pragma unroll
    for (int t = 0; t < 4; ++t) {
        int idx = t * 32 + lane;
        float e = 0.0f; int c = 0;
        if (idx < cnt) {
            c = cols[idx];
            float v = si + __ldg(dsth + c);
            v = v > 0.0f ? v : 0.2f * v;           // LeakyReLU (logits bounded -> no max)
            e = __expf(v);
        }
        s_wc[wid][idx] = make_float2(e, __int_as_float(c));
        sum += e;
    }
    #pragma unroll
    for (int o = 16; o; o >>= 1) sum += __shfl_xor_sync(0xffffffffu, sum, o);
    float inv = 1.0f / sum;
    __syncwarp();

    const float* Whh = Wh + (size_t)h * NN * 64 + 2 * lane;
    float2 A0 = {0, 0}, A1 = {0, 0}, A2 = {0, 0}, A3 = {0, 0};
    int j = 0;
    for (; j + 4 <= cnt; j += 4) {
        float2 p0 = s_wc[wid][j],     p1 = s_wc[wid][j + 1];
        float2 p2 = s_wc[wid][j + 2], p3 = s_wc[wid][j + 3];
        float2 v0 = *reinterpret_cast<const float2*>(Whh + (size_t)__float_as_int(p0.y) * 64);
        float2 v1 = *reinterpret_cast<const float2*>(Whh + (size_t)__float_as_int(p1.y) * 64);
        float2 v2 = *reinterpret_cast<const float2*>(Whh + (size_t)__float_as_int(p2.y) * 64);
        float2 v3 = *reinterpret_cast<const float2*>(Whh + (size_t)__float_as_int(p3.y) * 64);
        A0.x += p0.x * v0.x; A0.y += p0.x * v0.y;
        A1.x += p1.x * v1.x; A1.y += p1.x * v1.y;
        A2.x += p2.x * v2.x; A2.y += p2.x * v2.y;
        A3.x += p3.x * v3.x; A3.y += p3.x * v3.y;
    }
    for (; j < cnt; ++j) {
        float2 p0 = s_wc[wid][j];
        float2 v0 = *reinterpret_cast<const float2*>(Whh + (size_t)__float_as_int(p0.y) * 64);
        A0.x += p0.x * v0.x; A0.y += p0.x * v0.y;
    }
    float a0 = (A0.x + A1.x + A2.x + A3.x) * inv;
    float a1 = (A0.y + A1.y + A2.y + A3.y) * inv;
    a0 = a0 > 0.0f ? a0 : __expf(a0) - 1.0f;       // ELU
    a1 = a1 > 0.0f ? a1 : __expf(a1) - 1.0f;

    if (sel == 0) {
        unsigned short h0, l0, h1, l1;
        split_bf(a0, h0, l0); split_bf(a1, h1, l1);
        int o32 = row * 128 + h * 32 + lane;        // u32 index into [n][256] u16
        reinterpret_cast<uint32_t*>(g_cat_hi)[o32] = (uint32_t)h0 | ((uint32_t)h1 << 16);
        reinterpret_cast<uint32_t*>(g_cat_lo)[o32] = (uint32_t)l0 | ((uint32_t)l1 << 16);
    } else {
        float acc = 0.0f;
        #pragma unroll
        for (int k = 0; k < 32; ++k) {
            float w0 = __shfl_sync(0xffffffffu, a0, k);
            float w1 = __shfl_sync(0xffffffffu, a1, k);
            acc += w0 * W1[(2 * k) * 32 + lane] + w1 * W1[(2 * k + 1) * 32 + lane];
        }
        g_t1[(size_t)row * 32 + lane] = acc;
    }
}

// ---------------- 6: h1 = relu(nbrsum(t1)); t23 = h1@[W2|W3] ------------
__global__ void k_nbr_t23(const float* __restrict__ W2, const float* __restrict__ W3) {
    int wid = threadIdx.x >> 5, lane = threadIdx.x & 31;
    int row = blockIdx.x * 8 + wid;
    int cnt = g_cnt[row];
    const int* cols = g_cols + row * MAXNBR;
    float acc = 0.0f;
    for (int jj = 0; jj < cnt; ++jj) {
        int c = cols[jj];
        acc += g_t1[(size_t)c * 32 + lane];
    }
    float hv = fmaxf(acc, 0.0f);
    const float* W = (lane < 16) ? W2 : W3;
    int f = lane & 15;
    float acc2 = 0.0f;
    #pragma unroll
    for (int k = 0; k < 32; ++k) {
        float h = __shfl_sync(0xffffffffu, hv, k);
        acc2 += h * W[k * 16 + f];
    }
    g_t23[(size_t)row * 32 + lane] = acc2;
}

// ---------------- 7: mu/logvar = nbrsum, z = eps*exp(lv)+mu -------------
__global__ void k_final(const float* __restrict__ eps, float* __restrict__ out) {
    int wid = threadIdx.x >> 5, lane = threadIdx.x & 31;
    int row = blockIdx.x * 8 + wid;
    int cnt = g_cnt[row];
    const int* cols = g_cols + row * MAXNBR;
    float acc = 0.0f;
    for (int j = 0; j < cnt; ++j) {
        int c = cols[j];
        acc += g_t23[(size_t)c * 32 + lane];
    }
    float other = __shfl_xor_sync(0xffffffffu, acc, 16);
    size_t NNq = (size_t)NN * NN;
    if (lane < 16) {
        out[NNq + (size_t)row * 16 + lane] = acc;                          // mu
        float zz = eps[(size_t)row * 16 + lane] * __expf(other) + acc;
        g_z[(size_t)row * 16 + lane] = zz;
    } else {
        out[NNq + (size_t)NN * 16 + (size_t)row * 16 + (lane - 16)] = acc; // logvar
    }
}

// ---------------- 8: adj_rec = z @ z^T ----------------------------------
__global__ void k_adjrec(float* __restrict__ out) {
    __shared__ float zi[64 * 17];
    __shared__ float zj[64 * 17];
    int i0 = blockIdx.y * 64, j0 = blockIdx.x * 64;
    int tid = threadIdx.x;
    for (int l = tid; l < 1024; l += 256) {
        int r = l >> 4, k = l & 15;
        zi[r * 17 + k] = g_z[(size_t)(i0 + r) * 16 + k];
        zj[r * 17 + k] = g_z[(size_t)(j0 + r) * 16 + k];
    }
    __syncthreads();
    int ty = tid >> 4, tx = tid & 15;
    float acc[4][4] = {};
    #pragma unroll
    for (int k = 0; k < 16; ++k) {
        float av[4], bv[4];
        #pragma unroll
        for (int i = 0; i < 4; ++i) av[i] = zi[(ty * 4 + i) * 17 + k];
        #pragma unroll
        for (int j = 0; j < 4; ++j) bv[j] = zj[(tx * 4 + j) * 17 + k];
        #pragma unroll
        for (int i = 0; i < 4; ++i)
            #pragma unroll
            for (int j = 0; j < 4; ++j)
                acc[i][j] += av[i] * bv[j];
    }
    #pragma unroll
    for (int i = 0; i < 4; ++i) {
        float4 v = make_float4(acc[i][0], acc[i][1], acc[i][2], acc[i][3]);
        *reinterpret_cast<float4*>(out + (size_t)(i0 + ty * 4 + i) * NN + j0 + tx * 4) = v;
    }
}

// ---------------- launch ------------------------------------------------
extern "C" void kernel_launch(void* const* d_in, const int* in_sizes, int n_in,
                              void* d_out, int out_size) {
    const float* x       = (const float*)d_in[0];
    const float* adj     = (const float*)d_in[1];
    const float* W_heads = (const float*)d_in[2];
    const float* a_heads = (const float*)d_in[3];
    const float* W_att   = (const float*)d_in[4];
    const float* a_att   = (const float*)d_in[5];
    const float* W1      = (const float*)d_in[6];
    const float* W2      = (const float*)d_in[7];
    const float* W3      = (const float*)d_in[8];
    const float* eps     = (const float*)d_in[9];
    float* out = (float*)d_out;
    (void)in_sizes; (void)n_in; (void)out_size;

    k_build_csr<<<NN / 8, 256>>>(adj);
    k_prep_x<<<(NN * DD / 4) / 256, 256>>>(x);
    k_prep_w<<<(HH * DD * F1V + 256 * F1V) / 256, 256>>>(W_heads, W_att);
    k_gemm_mma<<<dim3(NN / 128, HH), 256>>>(a_heads, DD, 0);
    k_gat_aggr<<<(NN * HH) / 8, 256>>>(W1, 0);
    k_gemm_mma<<<dim3(NN / 128, 1), 256>>>(a_att, 256, 1);
    k_gat_aggr<<<NN / 8, 256>>>(W1, 1);
    k_nbr_t23<<<NN / 8, 256>>>(W2, W3);
    k_final<<<NN / 8, 256>>>(eps, out);
    k_adjrec<<<dim3(NN / 64, NN / 64), 256>>>(out);
}

// round 9
// speedup vs baseline: 1.8383x; 1.0282x over previous
#include <cuda_runtime.h>
#include <cuda_bf16.h>
#include <cstdint>

#define NN 4096
#define DD 512
#define F1V 64
#define HH 4
#define MAXNBR 128

__device__ __forceinline__ uint32_t smem_u32(const void* p) {
    uint32_t a;
    asm("{ .reg .u64 t; cvta.to.shared.u64 t, %1; cvt.u32.u64 %0, t; }" : "=r"(a) : "l"(p));
    return a;
}
__device__ __forceinline__ void mma_bf16(float* c, const uint32_t* a, const uint32_t* b) {
    asm volatile(
        "mma.sync.aligned.m16n8k16.row.col.f32.bf16.bf16.f32 "
        "{%0,%1,%2,%3}, {%4,%5,%6,%7}, {%8,%9}, {%0,%1,%2,%3};"
        : "+f"(c[0]), "+f"(c[1]), "+f"(c[2]), "+f"(c[3])
        : "r"(a[0]), "r"(a[1]), "r"(a[2]), "r"(a[3]), "r"(b[0]), "r"(b[1]));
}
__device__ __forceinline__ void ldsm4(uint32_t* r, uint32_t addr) {
    asm volatile("ldmatrix.sync.aligned.m8n8.x4.shared.b16 {%0,%1,%2,%3}, [%4];"
        : "=r"(r[0]), "=r"(r[1]), "=r"(r[2]), "=r"(r[3]) : "r"(addr));
}
__device__ __forceinline__ void split_bf(float f, unsigned short& hi, unsigned short& lo) {
    __nv_bfloat16 h = __float2bfloat16(f);
    float r = f - __bfloat162float(h);
    __nv_bfloat16 l = __float2bfloat16(r);
    hi = *reinterpret_cast<unsigned short*>(&h);
    lo = *reinterpret_cast<unsigned short*>(&l);
}

// ---------------- device scratch (static, no allocation) ----------------
__device__ int      g_cnt[NN];
__device__ int      g_cols[NN * MAXNBR];
__device__ uint16_t g_xhi[NN * DD];
__device__ uint16_t g_xlo[NN * DD];
__device__ uint16_t g_Wthi[HH * F1V * DD];     // [h][n][k] transposed
__device__ uint16_t g_Wtlo[HH * F1V * DD];
__device__ uint16_t g_Wathi[F1V * 256];        // [n][k]
__device__ uint16_t g_Watlo[F1V * 256];
__device__ float    g_Wh[HH * NN * F1V];       // [h][n][64]
__device__ float    g_src[HH * NN];
__device__ float    g_dst[HH * NN];
__device__ uint16_t g_cat_hi[NN * 256];        // [n][h*64+f]
__device__ uint16_t g_cat_lo[NN * 256];
__device__ float    g_Whc[NN * F1V];
__device__ float    g_srcc[NN];
__device__ float    g_dstc[NN];
__device__ float    g_t1[NN * 32];
__device__ float    g_t23[NN * 32];
__device__ float    g_z[NN * 16];

// ---------------- 1: CSR build (warp per row) ---------------------------
__global__ void k_build_csr(const float* __restrict__ adj) {
    int wid = threadIdx.x >> 5, lane = threadIdx.x & 31;
    int row = blockIdx.x * 8 + wid;
    const float4* arow = reinterpret_cast<const float4*>(adj + (size_t)row * NN);
    int cnt = 0;
    int* cols = g_cols + row * MAXNBR;
    for (int step = 0; step < 32; ++step) {
        float4 v = arow[step * 32 + lane];
        float vals[4] = {v.x, v.y, v.z, v.w};
        #pragma unroll
        for (int e = 0; e < 4; ++e) {
            bool p = vals[e] > 0.0f;
            unsigned m = __ballot_sync(0xffffffffu, p);
            if (p) {
                int pos = cnt + __popc(m & ((1u << lane) - 1u));
                if (pos < MAXNBR) cols[pos] = (step * 32 + lane) * 4 + e;
            }
            cnt += __popc(m);
        }
    }
    if (lane == 0) g_cnt[row] = cnt > MAXNBR ? MAXNBR : cnt;
}

// ---------------- 2: split x into bf16 hi/lo ----------------------------
__global__ void k_prep_x(const float* __restrict__ x) {
    int idx = blockIdx.x * 256 + threadIdx.x;       // over float4s
    float4 v = reinterpret_cast<const float4*>(x)[idx];
    unsigned short h0, l0, h1, l1, h2, l2, h3, l3;
    split_bf(v.x, h0, l0); split_bf(v.y, h1, l1);
    split_bf(v.z, h2, l2); split_bf(v.w, h3, l3);
    uint2 hv = make_uint2((uint32_t)h0 | ((uint32_t)h1 << 16),
                          (uint32_t)h2 | ((uint32_t)h3 << 16));
    uint2 lv = make_uint2((uint32_t)l0 | ((uint32_t)l1 << 16),
                          (uint32_t)l2 | ((uint32_t)l3 << 16));
    reinterpret_cast<uint2*>(g_xhi)[idx] = hv;
    reinterpret_cast<uint2*>(g_xlo)[idx] = lv;
}

// ---------------- 3: split+transpose weights ----------------------------
__global__ void k_prep_w(const float* __restrict__ W_heads, const float* __restrict__ W_att) {
    int idx = blockIdx.x * 256 + threadIdx.x;
    if (idx < HH * DD * F1V) {
        int n = idx & 63, k = (idx >> 6) & 511, h = idx >> 15;
        unsigned short hi, lo;
        split_bf(W_heads[idx], hi, lo);
        int o = (h * F1V + n) * DD + k;
        g_Wthi[o] = hi; g_Wtlo[o] = lo;
    } else {
        int i2 = idx - HH * DD * F1V;   // [256][64]
        int n = i2 & 63, k = i2 >> 6;
        unsigned short hi, lo;
        split_bf(W_att[i2], hi, lo);
        int o = n * 256 + k;
        g_Wathi[o] = hi; g_Watlo[o] = lo;
    }
}

// ---------------- 4: smem-pipelined mma GEMM (M=64,N=64) + src/dst ------
// k-chunk 16, 2 stages; stage block = A(hi|lo) 6144 + B(hi|lo) 6144 bytes.
//   A: stage*12288 + side*3072 + row*48 + unit*16   (rows 0..63)
//   B: stage*12288 + 6144 + side*3072 + row*48 + unit*16 (rows 0..63)
__global__ void __launch_bounds__(256)
k_gemm_mma(const float* __restrict__ avec, int K, int sel) {
    __shared__ __align__(16) unsigned char sm[24576];
    __shared__ float s_av[128];
    __shared__ float s_sp[4][64];
    __shared__ float s_dp[4][64];

    int tid = threadIdx.x;
    int w = tid >> 5, lane = tid & 31;
    int MW = (w & 1) * 32, NW = (w >> 1) * 16;
    int nwidx = w >> 1;
    int g = lane >> 2, t = lane & 3;
    int head = blockIdx.y;
    int m0 = blockIdx.x * 64;

    const uint16_t *Ahi, *Alo, *Bhi, *Blo;
    float *oWh, *oSrc, *oDst;
    if (sel == 0) {
        Ahi = g_xhi; Alo = g_xlo;
        Bhi = g_Wthi + (size_t)head * F1V * DD;
        Blo = g_Wtlo + (size_t)head * F1V * DD;
        oWh = g_Wh + (size_t)head * NN * F1V;
        oSrc = g_src + head * NN; oDst = g_dst + head * NN;
    } else {
        Ahi = g_cat_hi; Alo = g_cat_lo;
        Bhi = g_Wathi; Blo = g_Watlo;
        oWh = g_Whc; oSrc = g_srcc; oDst = g_dstc;
    }
    if (tid < 128) s_av[tid] = avec[head * 128 + tid];

    // LDG: each thread loads 1 A uint4 and 1 B uint4 per chunk
    int side = tid >> 7, row2 = (tid & 127) >> 1, half = tid & 1;
    const uint4* pA = reinterpret_cast<const uint4*>(
        (side ? Alo : Ahi) + (size_t)(m0 + row2) * K);
    const uint4* pB = reinterpret_cast<const uint4*>(
        (side ? Blo : Bhi) + (size_t)row2 * K);
    int stsA = side * 3072 + row2 * 48 + half * 16;
    int stsB = 6144 + side * 3072 + row2 * 48 + half * 16;

    // LDSM byte offsets (within stage block)
    uint32_t smb = smem_u32(sm);
    int offA0 = (MW + (lane & 15)) * 48 + (lane >> 4) * 16;
    int offA1 = offA0 + 16 * 48;
    int offB = 6144 + (NW + ((lane >> 4) << 3) + (lane & 7)) * 48 + ((lane >> 3) & 1) * 16;

    float acc[2][2][4] = {};
    int nch = K >> 4;

    // prologue: chunk 0 -> stage 0
    uint4 rA = pA[half], rB = pB[half];
    *reinterpret_cast<uint4*>(sm + stsA) = rA;
    *reinterpret_cast<uint4*>(sm + stsB) = rB;

    for (int c = 0; c < nch; ++c) {
        __syncthreads();
        if (c + 1 < nch) {
            rA = pA[(c + 1) * 2 + half];
            rB = pB[(c + 1) * 2 + half];
        }
        uint32_t st = smb + (c & 1) * 12288;
        uint32_t ah[2][4], al[2][4], bh[4], bl[4];
        ldsm4(ah[0], st + offA0);
        ldsm4(ah[1], st + offA1);
        ldsm4(al[0], st + 3072 + offA0);
        ldsm4(al[1], st + 3072 + offA1);
        ldsm4(bh, st + offB);
        ldsm4(bl, st + 3072 + offB);
        #pragma unroll
        for (int i = 0; i < 2; ++i)
            #pragma unroll
            for (int jj = 0; jj < 2; ++jj) {
                float* cc = acc[i][jj];
                mma_bf16(cc, ah[i], &bh[jj * 2]);
                mma_bf16(cc, al[i], &bh[jj * 2]);
                mma_bf16(cc, ah[i], &bl[jj * 2]);
            }
        if (c + 1 < nch) {
            int s2 = ((c + 1) & 1) * 12288;
            *reinterpret_cast<uint4*>(sm + s2 + stsA) = rA;
            *reinterpret_cast<uint4*>(sm + s2 + stsB) = rB;
        }
    }

    // epilogue: write Wh, fused src/dst partials
    #pragma unroll
    for (int i = 0; i < 2; ++i) {
        int r0 = MW + i * 16 + g;
        float sp0 = 0, sp1 = 0, dp0 = 0, dp1 = 0;
        #pragma unroll
        for (int jj = 0; jj < 2; ++jj) {
            int cb = NW + jj * 8 + 2 * t;
            *reinterpret_cast<float2*>(oWh + (size_t)(m0 + r0) * 64 + cb) =
                make_float2(acc[i][jj][0], acc[i][jj][1]);
            *reinterpret_cast<float2*>(oWh + (size_t)(m0 + r0 + 8) * 64 + cb) =
                make_float2(acc[i][jj][2], acc[i][jj][3]);
            float a0s = s_av[cb], a1s = s_av[cb + 1];
            float a0d = s_av[64 + cb], a1d = s_av[64 + cb + 1];
            sp0 += acc[i][jj][0] * a0s + acc[i][jj][1] * a1s;
            sp1 += acc[i][jj][2] * a0s + acc[i][jj][3] * a1s;
            dp0 += acc[i][jj][0] * a0d + acc[i][jj][1] * a1d;
            dp1 += acc[i][jj][2] * a0d + acc[i][jj][3] * a1d;
        }
        #pragma unroll
        for (int off = 1; off < 4; off <<= 1) {
            sp0 += __shfl_xor_sync(0xffffffffu, sp0, off);
            sp1 += __shfl_xor_sync(0xffffffffu, sp1, off);
            dp0 += __shfl_xor_sync(0xffffffffu, dp0, off);
            dp1 += __shfl_xor_sync(0xffffffffu, dp1, off);
        }
        if (t == 0) {
            s_sp[nwidx][r0] = sp0; s_sp[nwidx][r0 + 8] = sp1;
            s_dp[nwidx][r0] = dp0; s_dp[nwidx][r0 + 8] = dp1;
        }
    }
    __syncthreads();
    if (tid < 64) {
        oSrc[m0 + tid] = s_sp[0][tid] + s_sp[1][tid] + s_sp[2][tid] + s_sp[3][tid];
        oDst[m0 + tid] = s_dp[0][tid] + s_dp[1][tid] + s_dp[2][tid] + s_dp[3][tid];
    }
}

// ---------------- 5: sparse GAT softmax + aggregate + ELU ---------------
// half-warp per neighbor, float4 features; cross-half merge via shfl_xor(16)
__global__ void k_gat_aggr(const float* __restrict__ W1, int sel) {
    __shared__ float s_w[8][MAXNBR];
    __shared__ int   s_c[8][MAXNBR];
    int wid = threadIdx.x >> 5, lane = threadIdx.x & 31;
    int wg = blockIdx.x * 8 + wid;
    int h, row;
    if (sel) { h = 0; row = wg; } else { h = wg & 3; row = wg >> 2; }
    const float* Wh  = sel ? g_Whc  : g_Wh;
    const float* src = sel ? g_srcc : g_src;
    const float* dst = sel ? g_dstc : g_dst;

    int cnt = g_cnt[row];
    const int* cols = g_cols + row * MAXNBR;
    float si = src[h * NN + row];
    const float* dsth = dst + (size_t)h * NN;

    float sum = 0.0f;
    #pragma unroll
    for (int tt = 0; tt < 4; ++tt) {
        int idx = tt * 32 + lane;
        float e = 0.0f; int c = 0;
        if (idx < cnt) {
            c = cols[idx];
            float v = si + __ldg(dsth + c);
            v = v > 0.0f ? v : 0.2f * v;           // LeakyReLU (logits bounded -> no max)
            e = __expf(v);
        }
        s_w[wid][idx] = e;
        s_c[wid][idx] = c;
        sum += e;
    }
    #pragma unroll
    for (int o = 16; o; o >>= 1) sum += __shfl_xor_sync(0xffffffffu, sum, o);
    float inv = 1.0f / sum;
    __syncwarp();

    int half = lane >> 4, li = lane & 15;
    const float* WhhB = Wh + (size_t)h * NN * 64;
    float4 A0 = {0, 0, 0, 0}, A1 = {0, 0, 0, 0};
    int cntR = (cnt + 3) & ~3;
    for (int j = 0; j < cntR; j += 4) {
        int   c0 = s_c[wid][j + half],     c1 = s_c[wid][j + 2 + half];
        float w0 = s_w[wid][j + half],     w1 = s_w[wid][j + 2 + half];
        float4 v0 = __ldg(reinterpret_cast<const float4*>(WhhB + (size_t)c0 * 64) + li);
        float4 v1 = __ldg(reinterpret_cast<const float4*>(WhhB + (size_t)c1 * 64) + li);
        A0.x += w0 * v0.x; A0.y += w0 * v0.y; A0.z += w0 * v0.z; A0.w += w0 * v0.w;
        A1.x += w1 * v1.x; A1.y += w1 * v1.y; A1.z += w1 * v1.z; A1.w += w1 * v1.w;
    }
    float4 A;
    A.x = A0.x + A1.x; A.y = A0.y + A1.y; A.z = A0.z + A1.z; A.w = A0.w + A1.w;
    A.x += __shfl_xor_sync(0xffffffffu, A.x, 16);
    A.y += __shfl_xor_sync(0xffffffffu, A.y, 16);
    A.z += __shfl_xor_sync(0xffffffffu, A.z, 16);
    A.w += __shfl_xor_sync(0xffffffffu, A.w, 16);
    A.x *= inv; A.y *= inv; A.z *= inv; A.w *= inv;
    A.x = A.x > 0.0f ? A.x : __expf(A.x) - 1.0f;   // ELU
    A.y = A.y > 0.0f ? A.y : __expf(A.y) - 1.0f;
    A.z = A.z > 0.0f ? A.z : __expf(A.z) - 1.0f;
    A.w = A.w > 0.0f ? A.w : __expf(A.w) - 1.0f;

    if (sel == 0) {
        if (half == 0) {
            unsigned short h0, l0, h1, l1, h2, l2, h3, l3;
            split_bf(A.x, h0, l0); split_bf(A.y, h1, l1);
            split_bf(A.z, h2, l2); split_bf(A.w, h3, l3);
            int o2 = row * 64 + h * 16 + li;        // uint2 index
            reinterpret_cast<uint2*>(g_cat_hi)[o2] =
                make_uint2((uint32_t)h0 | ((uint32_t)h1 << 16),
                           (uint32_t)h2 | ((uint32_t)h3 << 16));
            reinterpret_cast<uint2*>(g_cat_lo)[o2] =
                make_uint2((uint32_t)l0 | ((uint32_t)l1 << 16),
                           (uint32_t)l2 | ((uint32_t)l3 << 16));
        }
    } else {
        // fused t1 = gc_row @ W1; gc features: lane li holds f = 4*li..4*li+3
        float acc = 0.0f;
        #pragma unroll
        for (int li2 = 0; li2 < 16; ++li2) {
            float w0 = __shfl_sync(0xffffffffu, A.x, li2);
            float w1 = __shfl_sync(0xffffffffu, A.y, li2);
            float w2 = __shfl_sync(0xffffffffu, A.z, li2);
            float w3 = __shfl_sync(0xffffffffu, A.w, li2);
            int kb = li2 * 4;
            acc += w0 * W1[kb * 32 + lane] + w1 * W1[(kb + 1) * 32 + lane]
                 + w2 * W1[(kb + 2) * 32 + lane] + w3 * W1[(kb + 3) * 32 + lane];
        }
        g_t1[(size_t)row * 32 + lane] = acc;
    }
}

// ---------------- 6: h1 = relu(nbrsum(t1)); t23 = h1@[W2|W3] ------------
__global__ void k_nbr_t23(const float* __restrict__ W2, const float* __restrict__ W3) {
    int wid = threadIdx.x >> 5, lane = threadIdx.x & 31;
    int row = blockIdx.x * 8 + wid;
    int cnt = g_cnt[row];
    const int* cols = g_cols + row * MAXNBR;
    float acc = 0.0f;
    for (int jj = 0; jj < cnt; ++jj) {
        int c = cols[jj];
        acc += g_t1[(size_t)c * 32 + lane];
    }
    float hv = fmaxf(acc, 0.0f);
    const float* W = (lane < 16) ? W2 : W3;
    int f = lane & 15;
    float acc2 = 0.0f;
    #pragma unroll
    for (int k = 0; k < 32; ++k) {
        float h = __shfl_sync(0xffffffffu, hv, k);
        acc2 += h * W[k * 16 + f];
    }
    g_t23[(size_t)row * 32 + lane] = acc2;
}

// ---------------- 7: mu/logvar = nbrsum, z = eps*exp(lv)+mu -------------
__global__ void k_final(const float* __restrict__ eps, float* __restrict__ out) {
    int wid = threadIdx.x >> 5, lane = threadIdx.x & 31;
    int row = blockIdx.x * 8 + wid;
    int cnt = g_cnt[row];
    const int* cols = g_cols + row * MAXNBR;
    float acc = 0.0f;
    for (int j = 0; j < cnt; ++j) {
        int c = cols[j];
        acc += g_t23[(size_t)c * 32 + lane];
    }
    float other = __shfl_xor_sync(0xffffffffu, acc, 16);
    size_t NNq = (size_t)NN * NN;
    if (lane < 16) {
        out[NNq + (size_t)row * 16 + lane] = acc;                          // mu
        float zz = eps[(size_t)row * 16 + lane] * __expf(other) + acc;
        g_z[(size_t)row * 16 + lane] = zz;
    } else {
        out[NNq + (size_t)NN * 16 + (size_t)row * 16 + (lane - 16)] = acc; // logvar
    }
}

// ---------------- 8: adj_rec = z @ z^T ----------------------------------
__global__ void k_adjrec(float* __restrict__ out) {
    __shared__ float zi[64 * 17];
    __shared__ float zj[64 * 17];
    int i0 = blockIdx.y * 64, j0 = blockIdx.x * 64;
    int tid = threadIdx.x;
    for (int l = tid; l < 1024; l += 256) {
        int r = l >> 4, k = l & 15;
        zi[r * 17 + k] = g_z[(size_t)(i0 + r) * 16 + k];
        zj[r * 17 + k] = g_z[(size_t)(j0 + r) * 16 + k];
    }
    __syncthreads();
    int ty = tid >> 4, tx = tid & 15;
    float acc[4][4] = {};
    #pragma unroll
    for (int k = 0; k < 16; ++k) {
        float av[4], bv[4];
        #pragma unroll
        for (int i = 0; i < 4; ++i) av[i] = zi[(ty * 4 + i) * 17 + k];
        #pragma unroll
        for (int j = 0; j < 4; ++j) bv[j] = zj[(tx * 4 + j) * 17 + k];
        #pragma unroll
        for (int i = 0; i < 4; ++i)
            #pragma unroll
            for (int j = 0; j < 4; ++j)
                acc[i][j] += av[i] * bv[j];
    }
    #pragma unroll
    for (int i = 0; i < 4; ++i) {
        float4 v = make_float4(acc[i][0], acc[i][1], acc[i][2], acc[i][3]);
        *reinterpret_cast<float4*>(out + (size_t)(i0 + ty * 4 + i) * NN + j0 + tx * 4) = v;
    }
}

// ---------------- launch ------------------------------------------------
extern "C" void kernel_launch(void* const* d_in, const int* in_sizes, int n_in,
                              void* d_out, int out_size) {
    const float* x       = (const float*)d_in[0];
    const float* adj     = (const float*)d_in[1];
    const float* W_heads = (const float*)d_in[2];
    const float* a_heads = (const float*)d_in[3];
    const float* W_att   = (const float*)d_in[4];
    const float* a_att   = (const float*)d_in[5];
    const float* W1      = (const float*)d_in[6];
    const float* W2      = (const float*)d_in[7];
    const float* W3      = (const float*)d_in[8];
    const float* eps     = (const float*)d_in[9];
    float* out = (float*)d_out;
    (void)in_sizes; (void)n_in; (void)out_size;

    k_build_csr<<<NN / 8, 256>>>(adj);
    k_prep_x<<<(NN * DD / 4) / 256, 256>>>(x);
    k_prep_w<<<(HH * DD * F1V + 256 * F1V) / 256, 256>>>(W_heads, W_att);
    k_gemm_mma<<<dim3(NN / 64, HH), 256>>>(a_heads, DD, 0);
    k_gat_aggr<<<(NN * HH) / 8, 256>>>(W1, 0);
    k_gemm_mma<<<dim3(NN / 64, 1), 256>>>(a_att, 256, 1);
    k_gat_aggr<<<NN / 8, 256>>>(W1, 1);
    k_nbr_t23<<<NN / 8, 256>>>(W2, W3);
    k_final<<<NN / 8, 256>>>(eps, out);
    k_adjrec<<<dim3(NN / 64, NN / 64), 256>>>(out);
}

// round 10
// speedup vs baseline: 1.9821x; 1.0782x over previous
#include <cuda_runtime.h>
#include <cuda_bf16.h>
#include <cstdint>

#define NN 4096
#define DD 512
#define F1V 64
#define HH 4
#define MAXNBR 128

__device__ __forceinline__ uint32_t smem_u32(const void* p) {
    uint32_t a;
    asm("{ .reg .u64 t; cvta.to.shared.u64 t, %1; cvt.u32.u64 %0, t; }" : "=r"(a) : "l"(p));
    return a;
}
__device__ __forceinline__ void mma_bf16(float* c, const uint32_t* a, const uint32_t* b) {
    asm volatile(
        "mma.sync.aligned.m16n8k16.row.col.f32.bf16.bf16.f32 "
        "{%0,%1,%2,%3}, {%4,%5,%6,%7}, {%8,%9}, {%0,%1,%2,%3};"
        : "+f"(c[0]), "+f"(c[1]), "+f"(c[2]), "+f"(c[3])
        : "r"(a[0]), "r"(a[1]), "r"(a[2]), "r"(a[3]), "r"(b[0]), "r"(b[1]));
}
__device__ __forceinline__ void ldsm4(uint32_t* r, uint32_t addr) {
    asm volatile("ldmatrix.sync.aligned.m8n8.x4.shared.b16 {%0,%1,%2,%3}, [%4];"
        : "=r"(r[0]), "=r"(r[1]), "=r"(r[2]), "=r"(r[3]) : "r"(addr));
}
__device__ __forceinline__ void split_bf(float f, unsigned short& hi, unsigned short& lo) {
    __nv_bfloat16 h = __float2bfloat16(f);
    float r = f - __bfloat162float(h);
    __nv_bfloat16 l = __float2bfloat16(r);
    hi = *reinterpret_cast<unsigned short*>(&h);
    lo = *reinterpret_cast<unsigned short*>(&l);
}

// ---------------- device scratch (static, no allocation) ----------------
__device__ int      g_cnt[NN];
__device__ int      g_cols[NN * MAXNBR];
__device__ uint16_t g_xhi[NN * DD];
__device__ uint16_t g_xlo[NN * DD];
__device__ uint16_t g_Wthi[HH * F1V * DD];     // [h][n][k] transposed
__device__ uint16_t g_Wtlo[HH * F1V * DD];
__device__ uint16_t g_Wathi[F1V * 256];        // [n][k]
__device__ uint16_t g_Watlo[F1V * 256];
__device__ float    g_Wh[HH * NN * F1V];       // [h][n][64]
__device__ float    g_src[HH * NN];
__device__ float    g_dst[HH * NN];
__device__ uint16_t g_cat_hi[NN * 256];        // [n][h*64+f]
__device__ uint16_t g_cat_lo[NN * 256];
__device__ float    g_Whc[NN * F1V];
__device__ float    g_srcc[NN];
__device__ float    g_dstc[NN];
__device__ float    g_t1[NN * 32];
__device__ float    g_t23[NN * 32];
__device__ float    g_z[NN * 16];

// ---------------- 1: CSR build (warp per row) ---------------------------
__global__ void k_build_csr(const float* __restrict__ adj) {
    int wid = threadIdx.x >> 5, lane = threadIdx.x & 31;
    int row = blockIdx.x * 8 + wid;
    const float4* arow = reinterpret_cast<const float4*>(adj + (size_t)row * NN);
    int cnt = 0;
    int* cols = g_cols + row * MAXNBR;
    for (int step = 0; step < 32; ++step) {
        float4 v = arow[step * 32 + lane];
        float vals[4] = {v.x, v.y, v.z, v.w};
        #pragma unroll
        for (int e = 0; e < 4; ++e) {
            bool p = vals[e] > 0.0f;
            unsigned m = __ballot_sync(0xffffffffu, p);
            if (p) {
                int pos = cnt + __popc(m & ((1u << lane) - 1u));
                if (pos < MAXNBR) cols[pos] = (step * 32 + lane) * 4 + e;
            }
            cnt += __popc(m);
        }
    }
    if (lane == 0) g_cnt[row] = cnt > MAXNBR ? MAXNBR : cnt;
}

// ---------------- 2: split x into bf16 hi/lo ----------------------------
__global__ void k_prep_x(const float* __restrict__ x) {
    int idx = blockIdx.x * 256 + threadIdx.x;       // over float4s
    float4 v = reinterpret_cast<const float4*>(x)[idx];
    unsigned short h0, l0, h1, l1, h2, l2, h3, l3;
    split_bf(v.x, h0, l0); split_bf(v.y, h1, l1);
    split_bf(v.z, h2, l2); split_bf(v.w, h3, l3);
    uint2 hv = make_uint2((uint32_t)h0 | ((uint32_t)h1 << 16),
                          (uint32_t)h2 | ((uint32_t)h3 << 16));
    uint2 lv = make_uint2((uint32_t)l0 | ((uint32_t)l1 << 16),
                          (uint32_t)l2 | ((uint32_t)l3 << 16));
    reinterpret_cast<uint2*>(g_xhi)[idx] = hv;
    reinterpret_cast<uint2*>(g_xlo)[idx] = lv;
}

// ---------------- 3: split+transpose weights ----------------------------
__global__ void k_prep_w(const float* __restrict__ W_heads, const float* __restrict__ W_att) {
    int idx = blockIdx.x * 256 + threadIdx.x;
    if (idx < HH * DD * F1V) {
        int n = idx & 63, k = (idx >> 6) & 511, h = idx >> 15;
        unsigned short hi, lo;
        split_bf(W_heads[idx], hi, lo);
        int o = (h * F1V + n) * DD + k;
        g_Wthi[o] = hi; g_Wtlo[o] = lo;
    } else {
        int i2 = idx - HH * DD * F1V;   // [256][64]
        int n = i2 & 63, k = i2 >> 6;
        unsigned short hi, lo;
        split_bf(W_att[i2], hi, lo);
        int o = n * 256 + k;
        g_Wathi[o] = hi; g_Watlo[o] = lo;
    }
}

// ---------------- 4: smem-pipelined mma GEMM (M=64,N=64) + src/dst ------
// k-chunk 32, 2 stages, rows padded to 80B (conflict-free LDSM: 5r mod 32 perm).
// stage layout: Ahi@0 (64*80), Alo@5120, Bhi@10240, Blo@15360; stage=20480B.
__global__ void __launch_bounds__(256)
k_gemm_mma(const float* __restrict__ avec, int K, int sel) {
    __shared__ __align__(16) unsigned char sm[2 * 20480];
    __shared__ float s_av[128];
    __shared__ float s_sp[4][64];
    __shared__ float s_dp[4][64];

    int tid = threadIdx.x;
    int w = tid >> 5, lane = tid & 31;
    int MW = (w & 1) * 32, NW = (w >> 1) * 16;
    int nwidx = w >> 1;
    int g = lane >> 2, t = lane & 3;
    int head = blockIdx.y;
    int m0 = blockIdx.x * 64;

    const uint16_t *Ahi, *Alo, *Bhi, *Blo;
    float *oWh, *oSrc, *oDst;
    if (sel == 0) {
        Ahi = g_xhi; Alo = g_xlo;
        Bhi = g_Wthi + (size_t)head * F1V * DD;
        Blo = g_Wtlo + (size_t)head * F1V * DD;
        oWh = g_Wh + (size_t)head * NN * F1V;
        oSrc = g_src + head * NN; oDst = g_dst + head * NN;
    } else {
        Ahi = g_cat_hi; Alo = g_cat_lo;
        Bhi = g_Wathi; Blo = g_Watlo;
        oWh = g_Whc; oSrc = g_srcc; oDst = g_dstc;
    }
    if (tid < 128) s_av[tid] = avec[head * 128 + tid];

    // LDG: thread t handles row = t>>2, 16B-unit u = t&3 for all four regions
    int rowT = tid >> 2, u = tid & 3;
    int Ku4 = K >> 3;                               // uint4 per row
    const uint4* pAh = reinterpret_cast<const uint4*>(Ahi) + (size_t)(m0 + rowT) * Ku4 + u;
    const uint4* pAl = reinterpret_cast<const uint4*>(Alo) + (size_t)(m0 + rowT) * Ku4 + u;
    const uint4* pBh = reinterpret_cast<const uint4*>(Bhi) + (size_t)rowT * Ku4 + u;
    const uint4* pBl = reinterpret_cast<const uint4*>(Blo) + (size_t)rowT * Ku4 + u;
    int stsOff = rowT * 80 + u * 16;

    // LDSM byte offsets within a stage (kbyte added per k-step)
    uint32_t smb = smem_u32(sm);
    int offA = (MW + (lane & 15)) * 80 + (lane >> 4) * 16;        // +16rows:*80*16, +ks*32
    int offB = 10240 + (NW + ((lane >> 4) << 3) + (lane & 7)) * 80 + ((lane >> 3) & 1) * 16;

    float acc[2][2][4] = {};
    int nch = K >> 5;

    // prologue: chunk 0 -> stage 0
    uint4 rAh = pAh[0], rAl = pAl[0], rBh = pBh[0], rBl = pBl[0];
    *reinterpret_cast<uint4*>(sm + stsOff) = rAh;
    *reinterpret_cast<uint4*>(sm + 5120 + stsOff) = rAl;
    *reinterpret_cast<uint4*>(sm + stsOff + 10240) = rBh;
    *reinterpret_cast<uint4*>(sm + 15360 + stsOff) = rBl;

    for (int c = 0; c < nch; ++c) {
        __syncthreads();
        if (c + 1 < nch) {
            int gi = (c + 1) * 4;
            rAh = pAh[gi]; rAl = pAl[gi]; rBh = pBh[gi]; rBl = pBl[gi];
        }
        uint32_t st = smb + (c & 1) * 20480;
        #pragma unroll
        for (int ks = 0; ks < 2; ++ks) {
            int kb = ks * 32;
            uint32_t ah[2][4], al[2][4], bh[4], bl[4];
            ldsm4(ah[0], st + offA + kb);
            ldsm4(ah[1], st + offA + 16 * 80 + kb);
            ldsm4(al[0], st + 5120 + offA + kb);
            ldsm4(al[1], st + 5120 + offA + 16 * 80 + kb);
            ldsm4(bh, st + offB + kb);
            ldsm4(bl, st + 5120 + offB + kb);
            #pragma unroll
            for (int i = 0; i < 2; ++i)
                #pragma unroll
                for (int jj = 0; jj < 2; ++jj) {
                    float* cc = acc[i][jj];
                    mma_bf16(cc, ah[i], &bh[jj * 2]);
                    mma_bf16(cc, al[i], &bh[jj * 2]);
                    mma_bf16(cc, ah[i], &bl[jj * 2]);
                }
        }
        if (c + 1 < nch) {
            unsigned char* s2 = sm + ((c + 1) & 1) * 20480;
            *reinterpret_cast<uint4*>(s2 + stsOff) = rAh;
            *reinterpret_cast<uint4*>(s2 + 5120 + stsOff) = rAl;
            *reinterpret_cast<uint4*>(s2 + stsOff + 10240) = rBh;
            *reinterpret_cast<uint4*>(s2 + 15360 + stsOff) = rBl;
        }
    }

    // epilogue: write Wh, fused src/dst partials
    #pragma unroll
    for (int i = 0; i < 2; ++i) {
        int r0 = MW + i * 16 + g;
        float sp0 = 0, sp1 = 0, dp0 = 0, dp1 = 0;
        #pragma unroll
        for (int jj = 0; jj < 2; ++jj) {
            int cb = NW + jj * 8 + 2 * t;
            *reinterpret_cast<float2*>(oWh + (size_t)(m0 + r0) * 64 + cb) =
                make_float2(acc[i][jj][0], acc[i][jj][1]);
            *reinterpret_cast<float2*>(oWh + (size_t)(m0 + r0 + 8) * 64 + cb) =
                make_float2(acc[i][jj][2], acc[i][jj][3]);
            float a0s = s_av[cb], a1s = s_av[cb + 1];
            float a0d = s_av[64 + cb], a1d = s_av[64 + cb + 1];
            sp0 += acc[i][jj][0] * a0s + acc[i][jj][1] * a1s;
            sp1 += acc[i][jj][2] * a0s + acc[i][jj][3] * a1s;
            dp0 += acc[i][jj][0] * a0d + acc[i][jj][1] * a1d;
            dp1 += acc[i][jj][2] * a0d + acc[i][jj][3] * a1d;
        }
        #pragma unroll
        for (int off = 1; off < 4; off <<= 1) {
            sp0 += __shfl_xor_sync(0xffffffffu, sp0, off);
            sp1 += __shfl_xor_sync(0xffffffffu, sp1, off);
            dp0 += __shfl_xor_sync(0xffffffffu, dp0, off);
            dp1 += __shfl_xor_sync(0xffffffffu, dp1, off);
        }
        if (t == 0) {
            s_sp[nwidx][r0] = sp0; s_sp[nwidx][r0 + 8] = sp1;
            s_dp[nwidx][r0] = dp0; s_dp[nwidx][r0 + 8] = dp1;
        }
    }
    __syncthreads();
    if (tid < 64) {
        oSrc[m0 + tid] = s_sp[0][tid] + s_sp[1][tid] + s_sp[2][tid] + s_sp[3][tid];
        oDst[m0 + tid] = s_dp[0][tid] + s_dp[1][tid] + s_dp[2][tid] + s_dp[3][tid];
    }
}

// ---------------- 5: sparse GAT softmax + aggregate + ELU ---------------
// half-warp per neighbor, float4 features; cross-half merge via shfl_xor(16)
__global__ void k_gat_aggr(const float* __restrict__ W1, int sel) {
    __shared__ float s_w[8][MAXNBR];
    __shared__ int   s_c[8][MAXNBR];
    int wid = threadIdx.x >> 5, lane = threadIdx.x & 31;
    int wg = blockIdx.x * 8 + wid;
    int h, row;
    if (sel) { h = 0; row = wg; } else { h = wg & 3; row = wg >> 2; }
    const float* Wh  = sel ? g_Whc  : g_Wh;
    const float* src = sel ? g_srcc : g_src;
    const float* dst = sel ? g_dstc : g_dst;

    int cnt = g_cnt[row];
    const int* cols = g_cols + row * MAXNBR;
    float si = src[h * NN + row];
    const float* dsth = dst + (size_t)h * NN;

    float sum = 0.0f;
    #pragma unroll
    for (int tt = 0; tt < 4; ++tt) {
        int idx = tt * 32 + lane;
        float e = 0.0f; int c = 0;
        if (idx < cnt) {
            c = cols[idx];
            float v = si + __ldg(dsth + c);
            v = v > 0.0f ? v : 0.2f * v;           // LeakyReLU (logits bounded -> no max)
            e = __expf(v);
        }
        s_w[wid][idx] = e;
        s_c[wid][idx] = c;
        sum += e;
    }
    #pragma unroll
    for (int o = 16; o; o >>= 1) sum += __shfl_xor_sync(0xffffffffu, sum, o);
    float inv = 1.0f / sum;
    __syncwarp();

    int half = lane >> 4, li = lane & 15;
    const float* WhhB = Wh + (size_t)h * NN * 64;
    float4 A0 = {0, 0, 0, 0}, A1 = {0, 0, 0, 0};
    int cntR = (cnt + 3) & ~3;
    for (int j = 0; j < cntR; j += 4) {
        int   c0 = s_c[wid][j + half],     c1 = s_c[wid][j + 2 + half];
        float w0 = s_w[wid][j + half],     w1 = s_w[wid][j + 2 + half];
        float4 v0 = __ldg(reinterpret_cast<const float4*>(WhhB + (size_t)c0 * 64) + li);
        float4 v1 = __ldg(reinterpret_cast<const float4*>(WhhB + (size_t)c1 * 64) + li);
        A0.x += w0 * v0.x; A0.y += w0 * v0.y; A0.z += w0 * v0.z; A0.w += w0 * v0.w;
        A1.x += w1 * v1.x; A1.y += w1 * v1.y; A1.z += w1 * v1.z; A1.w += w1 * v1.w;
    }
    float4 A;
    A.x = A0.x + A1.x; A.y = A0.y + A1.y; A.z = A0.z + A1.z; A.w = A0.w + A1.w;
    A.x += __shfl_xor_sync(0xffffffffu, A.x, 16);
    A.y += __shfl_xor_sync(0xffffffffu, A.y, 16);
    A.z += __shfl_xor_sync(0xffffffffu, A.z, 16);
    A.w += __shfl_xor_sync(0xffffffffu, A.w, 16);
    A.x *= inv; A.y *= inv; A.z *= inv; A.w *= inv;
    A.x = A.x > 0.0f ? A.x : __expf(A.x) - 1.0f;   // ELU
    A.y = A.y > 0.0f ? A.y : __expf(A.y) - 1.0f;
    A.z = A.z > 0.0f ? A.z : __expf(A.z) - 1.0f;
    A.w = A.w > 0.0f ? A.w : __expf(A.w) - 1.0f;

    if (sel == 0) {
        if (half == 0) {
            unsigned short h0, l0, h1, l1, h2, l2, h3, l3;
            split_bf(A.x, h0, l0); split_bf(A.y, h1, l1);
            split_bf(A.z, h2, l2); split_bf(A.w, h3, l3);
            int o2 = row * 64 + h * 16 + li;        // uint2 index
            reinterpret_cast<uint2*>(g_cat_hi)[o2] =
                make_uint2((uint32_t)h0 | ((uint32_t)h1 << 16),
                           (uint32_t)h2 | ((uint32_t)h3 << 16));
            reinterpret_cast<uint2*>(g_cat_lo)[o2] =
                make_uint2((uint32_t)l0 | ((uint32_t)l1 << 16),
                           (uint32_t)l2 | ((uint32_t)l3 << 16));
        }
    } else {
        // fused t1 = gc_row @ W1; gc features: lane li holds f = 4*li..4*li+3
        float acc = 0.0f;
        #pragma unroll
        for (int li2 = 0; li2 < 16; ++li2) {
            float w0 = __shfl_sync(0xffffffffu, A.x, li2);
            float w1 = __shfl_sync(0xffffffffu, A.y, li2);
            float w2 = __shfl_sync(0xffffffffu, A.z, li2);
            float w3 = __shfl_sync(0xffffffffu, A.w, li2);
            int kb = li2 * 4;
            acc += w0 * W1[kb * 32 + lane] + w1 * W1[(kb + 1) * 32 + lane]
                 + w2 * W1[(kb + 2) * 32 + lane] + w3 * W1[(kb + 3) * 32 + lane];
        }
        g_t1[(size_t)row * 32 + lane] = acc;
    }
}

// ---------------- 6: h1 = relu(nbrsum(t1)); t23 = h1@[W2|W3] ------------
__global__ void k_nbr_t23(const float* __restrict__ W2, const float* __restrict__ W3) {
    int wid = threadIdx.x >> 5, lane = threadIdx.x & 31;
    int row = blockIdx.x * 8 + wid;
    int cnt = g_cnt[row];
    const int* cols = g_cols + row * MAXNBR;
    float acc = 0.0f;
    for (int jj = 0; jj < cnt; ++jj) {
        int c = cols[jj];
        acc += g_t1[(size_t)c * 32 + lane];
    }
    float hv = fmaxf(acc, 0.0f);
    const float* W = (lane < 16) ? W2 : W3;
    int f = lane & 15;
    float acc2 = 0.0f;
    #pragma unroll
    for (int k = 0; k < 32; ++k) {
        float h = __shfl_sync(0xffffffffu, hv, k);
        acc2 += h * W[k * 16 + f];
    }
    g_t23[(size_t)row * 32 + lane] = acc2;
}

// ---------------- 7: mu/logvar = nbrsum, z = eps*exp(lv)+mu -------------
__global__ void k_final(const float* __restrict__ eps, float* __restrict__ out) {
    int wid = threadIdx.x >> 5, lane = threadIdx.x & 31;
    int row = blockIdx.x * 8 + wid;
    int cnt = g_cnt[row];
    const int* cols = g_cols + row * MAXNBR;
    float acc = 0.0f;
    for (int j = 0; j < cnt; ++j) {
        int c = cols[j];
        acc += g_t23[(size_t)c * 32 + lane];
    }
    float other = __shfl_xor_sync(0xffffffffu, acc, 16);
    size_t NNq = (size_t)NN * NN;
    if (lane < 16) {
        out[NNq + (size_t)row * 16 + lane] = acc;                          // mu
        float zz = eps[(size_t)row * 16 + lane] * __expf(other) + acc;
        g_z[(size_t)row * 16 + lane] = zz;
    } else {
        out[NNq + (size_t)NN * 16 + (size_t)row * 16 + (lane - 16)] = acc; // logvar
    }
}

// ---------------- 8: adj_rec = z @ z^T ----------------------------------
__global__ void k_adjrec(float* __restrict__ out) {
    __shared__ float zi[64 * 17];
    __shared__ float zj[64 * 17];
    int i0 = blockIdx.y * 64, j0 = blockIdx.x * 64;
    int tid = threadIdx.x;
    for (int l = tid; l < 1024; l += 256) {
        int r = l >> 4, k = l & 15;
        zi[r * 17 + k] = g_z[(size_t)(i0 + r) * 16 + k];
        zj[r * 17 + k] = g_z[(size_t)(j0 + r) * 16 + k];
    }
    __syncthreads();
    int ty = tid >> 4, tx = tid & 15;
    float acc[4][4] = {};
    #pragma unroll
    for (int k = 0; k < 16; ++k) {
        float av[4], bv[4];
        #pragma unroll
        for (int i = 0; i < 4; ++i) av[i] = zi[(ty * 4 + i) * 17 + k];
        #pragma unroll
        for (int j = 0; j < 4; ++j) bv[j] = zj[(tx * 4 + j) * 17 + k];
        #pragma unroll
        for (int i = 0; i < 4; ++i)
            #pragma unroll
            for (int j = 0; j < 4; ++j)
                acc[i][j] += av[i] * bv[j];
    }
    #pragma unroll
    for (int i = 0; i < 4; ++i) {
        float4 v = make_float4(acc[i][0], acc[i][1], acc[i][2], acc[i][3]);
        *reinterpret_cast<float4*>(out + (size_t)(i0 + ty * 4 + i) * NN + j0 + tx * 4) = v;
    }
}

// ---------------- launch ------------------------------------------------
extern "C" void kernel_launch(void* const* d_in, const int* in_sizes, int n_in,
                              void* d_out, int out_size) {
    const float* x       = (const float*)d_in[0];
    const float* adj     = (const float*)d_in[1];
    const float* W_heads = (const float*)d_in[2];
    const float* a_heads = (const float*)d_in[3];
    const float* W_att   = (const float*)d_in[4];
    const float* a_att   = (const float*)d_in[5];
    const float* W1      = (const float*)d_in[6];
    const float* W2      = (const float*)d_in[7];
    const float* W3      = (const float*)d_in[8];
    const float* eps     = (const float*)d_in[9];
    float* out = (float*)d_out;
    (void)in_sizes; (void)n_in; (void)out_size;

    k_build_csr<<<NN / 8, 256>>>(adj);
    k_prep_x<<<(NN * DD / 4) / 256, 256>>>(x);
    k_prep_w<<<(HH * DD * F1V + 256 * F1V) / 256, 256>>>(W_heads, W_att);
    k_gemm_mma<<<dim3(NN / 64, HH), 256>>>(a_heads, DD, 0);
    k_gat_aggr<<<(NN * HH) / 8, 256>>>(W1, 0);
    k_gemm_mma<<<dim3(NN / 64, 1), 256>>>(a_att, 256, 1);
    k_gat_aggr<<<NN / 8, 256>>>(W1, 1);
    k_nbr_t23<<<NN / 8, 256>>>(W2, W3);
    k_final<<<NN / 8, 256>>>(eps, out);
    k_adjrec<<<dim3(NN / 64, NN / 64), 256>>>(out);
}